// round 7
// baseline (speedup 1.0000x reference)
#include <cuda_runtime.h>

#define NP 65536          // cells per batch (256*256)
#define NCOLS 256
#define NBATCH 32
#define CTA 128

typedef unsigned long long u64;

__device__ __forceinline__ float tanh_f(float x) {
    float y; asm("tanh.approx.f32 %0, %1;" : "=f"(y) : "f"(x)); return y;
}
__device__ __forceinline__ float sig_f(float x) {
    return fmaf(0.5f, tanh_f(0.5f * x), 0.5f);
}
__device__ __forceinline__ u64 pack2(float a, float b) {
    u64 v; asm("mov.b64 %0, {%1, %2};" : "=l"(v) : "f"(a), "f"(b)); return v;
}
__device__ __forceinline__ void unpack2(u64 v, float& a, float& b) {
    asm("mov.b64 {%0, %1}, %2;" : "=f"(a), "=f"(b) : "l"(v));
}
// packed f32x2 FMA: acc.lo += m.lo*w.lo ; acc.hi += m.hi*w.hi
#define FMA2(acc, m, w) asm("fma.rn.f32x2 %0, %1, %2, %0;" : "+l"(acc) : "l"(m), "l"(w))

// One 16-gate block (blk in {0:i,1:f,2:g,3:o}) for two cells, gate-pair packed.
__device__ __forceinline__ void gate_block2(
    const float* sWx, const float* sWh, const u64* sB64, int blk,
    const float* x0, const float* x1,
    const float* h0, const float* h1,
    u64* a0, u64* a1)
{
    const u64* bp = sB64 + blk * 8;
    #pragma unroll
    for (int j = 0; j < 8; j++) { u64 bv = bp[j]; a0[j] = bv; a1[j] = bv; }

    #pragma unroll
    for (int k = 0; k < 9; k++) {
        const ulonglong2* wr = (const ulonglong2*)(sWx + k * 64 + blk * 16);
        u64 xa = pack2(x0[k], x0[k]);
        u64 xb = pack2(x1[k], x1[k]);
        #pragma unroll
        for (int q = 0; q < 4; q++) {
            ulonglong2 w = wr[q];
            FMA2(a0[2*q+0], xa, w.x); FMA2(a1[2*q+0], xb, w.x);
            FMA2(a0[2*q+1], xa, w.y); FMA2(a1[2*q+1], xb, w.y);
        }
    }
    #pragma unroll
    for (int k = 0; k < 16; k++) {
        const ulonglong2* wr = (const ulonglong2*)(sWh + k * 64 + blk * 16);
        u64 ha = pack2(h0[k], h0[k]);
        u64 hb = pack2(h1[k], h1[k]);
        #pragma unroll
        for (int q = 0; q < 4; q++) {
            ulonglong2 w = wr[q];
            FMA2(a0[2*q+0], ha, w.x); FMA2(a1[2*q+0], hb, w.x);
            FMA2(a0[2*q+1], ha, w.y); FMA2(a1[2*q+1], hb, w.y);
        }
    }
}

__device__ __forceinline__ void unpack_block(const u64* a, float* out) {
    #pragma unroll
    for (int j = 0; j < 8; j++) unpack2(a[j], out[2*j], out[2*j+1]);
}

// Shuffle-based lateral gather for one cell. Warp = 32 consecutive columns of
// one row. Fills x[1..8] (directions TL,T,TR,L,R,BL,B,BR).
__device__ __forceinline__ void gather_lat(
    const float* __restrict__ lo,   // lat_out batch base (b*NP*8)
    const float* __restrict__ li,   // lat_in  cell base  (cell*8)
    int p, int cc, int lane, bool topOk, bool botOk,
    float* x)
{
    const unsigned FULL = 0xffffffffu;
    // ---- row above: elems 0,1,2 ----
    if (topOk) {
        float4 u = *(const float4*)(lo + (size_t)(p - NCOLS) * 8);
        float tT  = u.y;
        float tTL = __shfl_up_sync(FULL, u.x, 1);
        float tTR = __shfl_down_sync(FULL, u.z, 1);
        if (lane == 0)
            tTL = (cc == 0) ? li[0] : lo[(size_t)(p - NCOLS - 1) * 8 + 0];
        if (lane == 31)
            tTR = (cc == NCOLS - 1) ? li[2] : lo[(size_t)(p - NCOLS + 1) * 8 + 2];
        x[1] = tTL; x[2] = tT; x[3] = tTR;
    } else {
        x[1] = li[0]; x[2] = li[1]; x[3] = li[2];
    }
    // ---- own row: elems 3,4 ----
    {
        float4 oa = *(const float4*)(lo + (size_t)p * 8);
        float4 ob = *(const float4*)(lo + (size_t)p * 8 + 4);
        float tL = __shfl_up_sync(FULL, oa.w, 1);
        float tR = __shfl_down_sync(FULL, ob.x, 1);
        if (lane == 0)
            tL = (cc == 0) ? li[3] : lo[(size_t)(p - 1) * 8 + 3];
        if (lane == 31)
            tR = (cc == NCOLS - 1) ? li[4] : lo[(size_t)(p + 1) * 8 + 4];
        x[4] = tL; x[5] = tR;
    }
    // ---- row below: elems 5,6,7 ----
    if (botOk) {
        float4 d = *(const float4*)(lo + (size_t)(p + NCOLS) * 8 + 4);
        float tB  = d.z;
        float tBL = __shfl_up_sync(FULL, d.y, 1);
        float tBR = __shfl_down_sync(FULL, d.w, 1);
        if (lane == 0)
            tBL = (cc == 0) ? li[5] : lo[(size_t)(p + NCOLS - 1) * 8 + 5];
        if (lane == 31)
            tBR = (cc == NCOLS - 1) ? li[7] : lo[(size_t)(p + NCOLS + 1) * 8 + 7];
        x[6] = tBL; x[7] = tB; x[8] = tBR;
    } else {
        x[6] = li[5]; x[7] = li[6]; x[8] = li[7];
    }
}

__global__ __launch_bounds__(CTA, 3) void knet_kernel(
    const float* __restrict__ dyn_in,
    const float* __restrict__ lat_in_g,
    const float* __restrict__ lat_out_g,
    const float* __restrict__ h_g,
    const float* __restrict__ c_g,
    const float* __restrict__ Wx,
    const float* __restrict__ Wh,
    const float* __restrict__ bvec,
    const float* __restrict__ Wo,
    const float* __restrict__ bo,
    float* __restrict__ out_dyn,
    float* __restrict__ out_lat,
    float* __restrict__ out_h,
    float* __restrict__ out_c)
{
    __shared__ __align__(16) float sWx[9 * 64];
    __shared__ __align__(16) float sWh[16 * 64];
    __shared__ __align__(16) float sB[64];
    __shared__ __align__(16) float sWoT[9 * 16];   // sWoT[j*16+k] = Wo[k*9+j]
    __shared__ float sBo[12];

    for (int i = threadIdx.x; i < 9 * 64; i += CTA) sWx[i] = Wx[i];
    for (int i = threadIdx.x; i < 16 * 64; i += CTA) sWh[i] = Wh[i];
    if (threadIdx.x < 64) sB[threadIdx.x] = bvec[threadIdx.x];
    for (int i = threadIdx.x; i < 144; i += CTA) {
        int k = i / 9, j = i % 9;
        sWoT[j * 16 + k] = Wo[i];
    }
    if (threadIdx.x < 9) sBo[threadIdx.x] = bo[threadIdx.x];
    __syncthreads();

    int tid = blockIdx.x * CTA + threadIdx.x;   // 0 .. 16*NP-1
    int p   = tid & (NP - 1);
    int b0  = tid >> 16;       // 0..15
    int b1  = b0 + 16;
    int lane = threadIdx.x & 31;

    int r  = p >> 8;
    int cc = p & (NCOLS - 1);
    bool topOk = (r > 0);
    bool botOk = (r < 255);

    size_t cell0 = (size_t)b0 * NP + p;
    size_t cell1 = (size_t)b1 * NP + p;

    // ---------------- gather x = [dyn, lat_in(updated)] ----------------
    float x0[9], x1[9];
    x0[0] = dyn_in[cell0];
    x1[0] = dyn_in[cell1];
    gather_lat(lat_out_g + ((size_t)b0 * NP) * 8, lat_in_g + cell0 * 8,
               p, cc, lane, topOk, botOk, x0);
    gather_lat(lat_out_g + ((size_t)b1 * NP) * 8, lat_in_g + cell1 * 8,
               p, cc, lane, topOk, botOk, x1);

    // ---------------- load h ----------------
    float h0[16], h1[16];
    {
        const float4* hp0 = (const float4*)(h_g + cell0 * 16);
        const float4* hp1 = (const float4*)(h_g + cell1 * 16);
        #pragma unroll
        for (int q = 0; q < 4; q++) {
            float4 v0 = hp0[q], v1 = hp1[q];
            h0[4*q+0] = v0.x; h0[4*q+1] = v0.y; h0[4*q+2] = v0.z; h0[4*q+3] = v0.w;
            h1[4*q+0] = v1.x; h1[4*q+1] = v1.y; h1[4*q+2] = v1.z; h1[4*q+3] = v1.w;
        }
    }

    const u64* sB64 = (const u64*)sB;
    u64 a0[8], a1[8];
    float t0[16], t1[16];
    float keep0[16], keep1[16];   // holds g, then i*g, then c_new

    // ---- block 2: g = tanh(...) ----
    gate_block2(sWx, sWh, sB64, 2, x0, x1, h0, h1, a0, a1);
    unpack_block(a0, t0); unpack_block(a1, t1);
    #pragma unroll
    for (int j = 0; j < 16; j++) { keep0[j] = tanh_f(t0[j]); keep1[j] = tanh_f(t1[j]); }

    // ---- block 0: i = sigmoid(...); keep = i*g ----
    gate_block2(sWx, sWh, sB64, 0, x0, x1, h0, h1, a0, a1);
    unpack_block(a0, t0); unpack_block(a1, t1);
    #pragma unroll
    for (int j = 0; j < 16; j++) {
        keep0[j] = sig_f(t0[j]) * keep0[j];
        keep1[j] = sig_f(t1[j]) * keep1[j];
    }

    // ---- block 1: f = sigmoid(...); keep = c_new = f*c + i*g ----
    gate_block2(sWx, sWh, sB64, 1, x0, x1, h0, h1, a0, a1);
    unpack_block(a0, t0); unpack_block(a1, t1);
    {
        const float4* cp0 = (const float4*)(c_g + cell0 * 16);
        const float4* cp1 = (const float4*)(c_g + cell1 * 16);
        #pragma unroll
        for (int q = 0; q < 4; q++) {
            float4 cv0 = cp0[q], cv1 = cp1[q];
            keep0[4*q+0] = fmaf(sig_f(t0[4*q+0]), cv0.x, keep0[4*q+0]);
            keep0[4*q+1] = fmaf(sig_f(t0[4*q+1]), cv0.y, keep0[4*q+1]);
            keep0[4*q+2] = fmaf(sig_f(t0[4*q+2]), cv0.z, keep0[4*q+2]);
            keep0[4*q+3] = fmaf(sig_f(t0[4*q+3]), cv0.w, keep0[4*q+3]);
            keep1[4*q+0] = fmaf(sig_f(t1[4*q+0]), cv1.x, keep1[4*q+0]);
            keep1[4*q+1] = fmaf(sig_f(t1[4*q+1]), cv1.y, keep1[4*q+1]);
            keep1[4*q+2] = fmaf(sig_f(t1[4*q+2]), cv1.z, keep1[4*q+2]);
            keep1[4*q+3] = fmaf(sig_f(t1[4*q+3]), cv1.w, keep1[4*q+3]);
        }
    }

    // write c_new
    {
        float4* cp0 = (float4*)(out_c + cell0 * 16);
        float4* cp1 = (float4*)(out_c + cell1 * 16);
        #pragma unroll
        for (int q = 0; q < 4; q++) {
            cp0[q] = make_float4(keep0[4*q+0], keep0[4*q+1], keep0[4*q+2], keep0[4*q+3]);
            cp1[q] = make_float4(keep1[4*q+0], keep1[4*q+1], keep1[4*q+2], keep1[4*q+3]);
        }
    }

    // ---- block 3: o = sigmoid(...); h_new = o * tanh(c_new) ----
    gate_block2(sWx, sWh, sB64, 3, x0, x1, h0, h1, a0, a1);
    unpack_block(a0, t0); unpack_block(a1, t1);
    float hn0[16], hn1[16];
    #pragma unroll
    for (int j = 0; j < 16; j++) {
        hn0[j] = sig_f(t0[j]) * tanh_f(keep0[j]);
        hn1[j] = sig_f(t1[j]) * tanh_f(keep1[j]);
    }

    // write h_new
    {
        float4* hp0 = (float4*)(out_h + cell0 * 16);
        float4* hp1 = (float4*)(out_h + cell1 * 16);
        #pragma unroll
        for (int q = 0; q < 4; q++) {
            hp0[q] = make_float4(hn0[4*q+0], hn0[4*q+1], hn0[4*q+2], hn0[4*q+3]);
            hp1[q] = make_float4(hn1[4*q+0], hn1[4*q+1], hn1[4*q+2], hn1[4*q+3]);
        }
    }

    // ---------------- output projection: out = tanh(h_new @ Wo + bo) ----------------
    float o0[9], o1[9];
    #pragma unroll
    for (int j = 0; j < 9; j++) {
        float a0s = sBo[j], a1s = sBo[j];
        const float4* wr = (const float4*)(sWoT + j * 16);
        #pragma unroll
        for (int q = 0; q < 4; q++) {
            float4 w = wr[q];
            a0s = fmaf(hn0[4*q+0], w.x, a0s); a1s = fmaf(hn1[4*q+0], w.x, a1s);
            a0s = fmaf(hn0[4*q+1], w.y, a0s); a1s = fmaf(hn1[4*q+1], w.y, a1s);
            a0s = fmaf(hn0[4*q+2], w.z, a0s); a1s = fmaf(hn1[4*q+2], w.z, a1s);
            a0s = fmaf(hn0[4*q+3], w.w, a0s); a1s = fmaf(hn1[4*q+3], w.w, a1s);
        }
        o0[j] = tanh_f(a0s);
        o1[j] = tanh_f(a1s);
    }

    out_dyn[cell0] = o0[0];
    out_dyn[cell1] = o1[0];
    {
        float4* lp0 = (float4*)(out_lat + cell0 * 8);
        float4* lp1 = (float4*)(out_lat + cell1 * 8);
        lp0[0] = make_float4(o0[1], o0[2], o0[3], o0[4]);
        lp0[1] = make_float4(o0[5], o0[6], o0[7], o0[8]);
        lp1[0] = make_float4(o1[1], o1[2], o1[3], o1[4]);
        lp1[1] = make_float4(o1[5], o1[6], o1[7], o1[8]);
    }
}

extern "C" void kernel_launch(void* const* d_in, const int* in_sizes, int n_in,
                              void* d_out, int out_size) {
    const float* dyn_in   = (const float*)d_in[0];
    const float* lat_in   = (const float*)d_in[1];
    const float* lat_out  = (const float*)d_in[2];
    const float* h        = (const float*)d_in[3];
    const float* c        = (const float*)d_in[4];
    const float* Wx       = (const float*)d_in[5];
    const float* Wh       = (const float*)d_in[6];
    const float* bvec     = (const float*)d_in[7];
    const float* Wo       = (const float*)d_in[8];
    const float* bo       = (const float*)d_in[9];
    // d_in[10..12] = pos0 / coming_from / going_to : adjacency recomputed analytically.

    float* out = (float*)d_out;
    float* out_dyn = out;                                   // [B, P, 1]
    float* out_lat = out_dyn + (size_t)NBATCH * NP;         // [B, P, 8]
    float* out_h   = out_lat + (size_t)NBATCH * NP * 8;     // [B, P, 16]
    float* out_c   = out_h   + (size_t)NBATCH * NP * 16;    // [B, P, 16]

    int total_threads = (NBATCH / 2) * NP;   // 2 cells (batch halves) per thread
    int blocks = total_threads / CTA;
    knet_kernel<<<blocks, CTA>>>(dyn_in, lat_in, lat_out, h, c,
                                 Wx, Wh, bvec, Wo, bo,
                                 out_dyn, out_lat, out_h, out_c);
}

// round 10
// speedup vs baseline: 1.0696x; 1.0696x over previous
#include <cuda_runtime.h>

#define NP 65536          // cells per batch (256*256)
#define NCOLS 256
#define NBATCH 32
#define CTA 128

typedef unsigned long long u64;

__device__ __forceinline__ float tanh_f(float x) {
    float y; asm("tanh.approx.f32 %0, %1;" : "=f"(y) : "f"(x)); return y;
}
__device__ __forceinline__ float sig_f(float x) {
    return fmaf(0.5f, tanh_f(0.5f * x), 0.5f);
}
__device__ __forceinline__ u64 pack2(float a, float b) {
    u64 v; asm("mov.b64 %0, {%1, %2};" : "=l"(v) : "f"(a), "f"(b)); return v;
}
__device__ __forceinline__ void unpack2(u64 v, float& a, float& b) {
    asm("mov.b64 {%0, %1}, %2;" : "=f"(a), "=f"(b) : "l"(v));
}
// packed f32x2 FMA: acc.lo += m.lo*w.lo ; acc.hi += m.hi*w.hi
#define FMA2(acc, m, w) asm("fma.rn.f32x2 %0, %1, %2, %0;" : "+l"(acc) : "l"(m), "l"(w))

// One 16-gate block (blk in {0:i,1:f,2:g,3:o}) for two cells, gate-pair packed.
// Weight pairs come straight out of LDS.128 (ulonglong2); the per-k scalar
// (x or h) is duplicated on the fly (1 MOV, alu pipe).
__device__ __forceinline__ void gate_block2(
    const float* sWx, const float* sWh, const u64* sB64, int blk,
    const float* x0, const float* x1,
    const float* h0, const float* h1,
    u64* a0, u64* a1)
{
    const u64* bp = sB64 + blk * 8;
    #pragma unroll
    for (int j = 0; j < 8; j++) { u64 bv = bp[j]; a0[j] = bv; a1[j] = bv; }

    #pragma unroll
    for (int k = 0; k < 9; k++) {
        const ulonglong2* wr = (const ulonglong2*)(sWx + k * 64 + blk * 16);
        u64 xa = pack2(x0[k], x0[k]);
        u64 xb = pack2(x1[k], x1[k]);
        #pragma unroll
        for (int q = 0; q < 4; q++) {
            ulonglong2 w = wr[q];
            FMA2(a0[2*q+0], xa, w.x); FMA2(a1[2*q+0], xb, w.x);
            FMA2(a0[2*q+1], xa, w.y); FMA2(a1[2*q+1], xb, w.y);
        }
    }
    #pragma unroll
    for (int k = 0; k < 16; k++) {
        const ulonglong2* wr = (const ulonglong2*)(sWh + k * 64 + blk * 16);
        u64 ha = pack2(h0[k], h0[k]);
        u64 hb = pack2(h1[k], h1[k]);
        #pragma unroll
        for (int q = 0; q < 4; q++) {
            ulonglong2 w = wr[q];
            FMA2(a0[2*q+0], ha, w.x); FMA2(a1[2*q+0], hb, w.x);
            FMA2(a0[2*q+1], ha, w.y); FMA2(a1[2*q+1], hb, w.y);
        }
    }
}

__device__ __forceinline__ void unpack_block(const u64* a, float* out) {
    #pragma unroll
    for (int j = 0; j < 8; j++) unpack2(a[j], out[2*j], out[2*j+1]);
}

__global__ __launch_bounds__(CTA, 4) void knet_kernel(
    const float* __restrict__ dyn_in,
    const float* __restrict__ lat_in_g,
    const float* __restrict__ lat_out_g,
    const float* __restrict__ h_g,
    const float* __restrict__ c_g,
    const float* __restrict__ Wx,
    const float* __restrict__ Wh,
    const float* __restrict__ bvec,
    const float* __restrict__ Wo,
    const float* __restrict__ bo,
    float* __restrict__ out_dyn,
    float* __restrict__ out_lat,
    float* __restrict__ out_h,
    float* __restrict__ out_c)
{
    __shared__ __align__(16) float sWx[9 * 64];
    __shared__ __align__(16) float sWh[16 * 64];
    __shared__ __align__(16) float sB[64];
    __shared__ __align__(16) float sWoT[9 * 16];   // sWoT[j*16+k] = Wo[k*9+j]
    __shared__ float sBo[12];

    for (int i = threadIdx.x; i < 9 * 64; i += CTA) sWx[i] = Wx[i];
    for (int i = threadIdx.x; i < 16 * 64; i += CTA) sWh[i] = Wh[i];
    if (threadIdx.x < 64) sB[threadIdx.x] = bvec[threadIdx.x];
    for (int i = threadIdx.x; i < 144; i += CTA) {
        int k = i / 9, j = i % 9;
        sWoT[j * 16 + k] = Wo[i];
    }
    if (threadIdx.x < 9) sBo[threadIdx.x] = bo[threadIdx.x];
    __syncthreads();

    int tid = blockIdx.x * CTA + threadIdx.x;   // 0 .. 16*NP-1
    int p   = tid & (NP - 1);
    int b0  = tid >> 16;       // 0..15
    int b1  = b0 + 16;

    int r  = p >> 8;
    int cc = p & (NCOLS - 1);

    size_t cell0 = (size_t)b0 * NP + p;
    size_t cell1 = (size_t)b1 * NP + p;

    // ---------------- gather x = [dyn, lat_in(updated)] ----------------
    float x0[9], x1[9];
    x0[0] = dyn_in[cell0];
    x1[0] = dyn_in[cell1];
    {
        const float* lo0 = lat_out_g + ((size_t)b0 * NP) * 8;  // batch base
        const float* lo1 = lat_out_g + ((size_t)b1 * NP) * 8;
        const int drs[8] = {-1,-1,-1, 0, 0, 1, 1, 1};
        const int dcs[8] = {-1, 0, 1,-1, 1,-1, 0, 1};

        bool interior = (r > 0) & (r < 255) & (cc > 0) & (cc < 255);
        if (__all_sync(0xffffffffu, interior)) {
            // warp-uniform fast path: no border fallbacks, no predication
            #pragma unroll
            for (int d = 0; d < 8; d++) {
                int nb = (r + drs[d]) * NCOLS + (cc + dcs[d]);
                x0[1 + d] = lo0[(size_t)nb * 8 + d];
                x1[1 + d] = lo1[(size_t)nb * 8 + d];
            }
        } else {
            const float* li0 = lat_in_g + cell0 * 8;
            const float* li1 = lat_in_g + cell1 * 8;
            #pragma unroll
            for (int d = 0; d < 8; d++) {
                int nr = r + drs[d], nc = cc + dcs[d];
                bool valid = ((unsigned)nr < 256u) && ((unsigned)nc < 256u);
                int nb = nr * NCOLS + nc;
                float v0, v1;
                if (valid) {
                    v0 = lo0[(size_t)nb * 8 + d];
                    v1 = lo1[(size_t)nb * 8 + d];
                } else {
                    v0 = li0[d];
                    v1 = li1[d];
                }
                x0[1 + d] = v0;
                x1[1 + d] = v1;
            }
        }
    }

    // ---------------- load h ----------------
    float h0[16], h1[16];
    {
        const float4* hp0 = (const float4*)(h_g + cell0 * 16);
        const float4* hp1 = (const float4*)(h_g + cell1 * 16);
        #pragma unroll
        for (int q = 0; q < 4; q++) {
            float4 v0 = hp0[q], v1 = hp1[q];
            h0[4*q+0] = v0.x; h0[4*q+1] = v0.y; h0[4*q+2] = v0.z; h0[4*q+3] = v0.w;
            h1[4*q+0] = v1.x; h1[4*q+1] = v1.y; h1[4*q+2] = v1.z; h1[4*q+3] = v1.w;
        }
    }

    const u64* sB64 = (const u64*)sB;
    u64 a0[8], a1[8];
    float t0[16], t1[16];
    float keep0[16], keep1[16];   // holds g, then i*g, then c_new

    // ---- block 2: g = tanh(...) ----
    gate_block2(sWx, sWh, sB64, 2, x0, x1, h0, h1, a0, a1);
    unpack_block(a0, t0); unpack_block(a1, t1);
    #pragma unroll
    for (int j = 0; j < 16; j++) { keep0[j] = tanh_f(t0[j]); keep1[j] = tanh_f(t1[j]); }

    // ---- block 0: i = sigmoid(...); keep = i*g ----
    gate_block2(sWx, sWh, sB64, 0, x0, x1, h0, h1, a0, a1);
    unpack_block(a0, t0); unpack_block(a1, t1);
    #pragma unroll
    for (int j = 0; j < 16; j++) {
        keep0[j] = sig_f(t0[j]) * keep0[j];
        keep1[j] = sig_f(t1[j]) * keep1[j];
    }

    // ---- block 1: f = sigmoid(...); keep = c_new = f*c + i*g ----
    gate_block2(sWx, sWh, sB64, 1, x0, x1, h0, h1, a0, a1);
    unpack_block(a0, t0); unpack_block(a1, t1);
    {
        const float4* cp0 = (const float4*)(c_g + cell0 * 16);
        const float4* cp1 = (const float4*)(c_g + cell1 * 16);
        #pragma unroll
        for (int q = 0; q < 4; q++) {
            float4 cv0 = cp0[q], cv1 = cp1[q];
            keep0[4*q+0] = fmaf(sig_f(t0[4*q+0]), cv0.x, keep0[4*q+0]);
            keep0[4*q+1] = fmaf(sig_f(t0[4*q+1]), cv0.y, keep0[4*q+1]);
            keep0[4*q+2] = fmaf(sig_f(t0[4*q+2]), cv0.z, keep0[4*q+2]);
            keep0[4*q+3] = fmaf(sig_f(t0[4*q+3]), cv0.w, keep0[4*q+3]);
            keep1[4*q+0] = fmaf(sig_f(t1[4*q+0]), cv1.x, keep1[4*q+0]);
            keep1[4*q+1] = fmaf(sig_f(t1[4*q+1]), cv1.y, keep1[4*q+1]);
            keep1[4*q+2] = fmaf(sig_f(t1[4*q+2]), cv1.z, keep1[4*q+2]);
            keep1[4*q+3] = fmaf(sig_f(t1[4*q+3]), cv1.w, keep1[4*q+3]);
        }
    }

    // write c_new
    {
        float4* cp0 = (float4*)(out_c + cell0 * 16);
        float4* cp1 = (float4*)(out_c + cell1 * 16);
        #pragma unroll
        for (int q = 0; q < 4; q++) {
            cp0[q] = make_float4(keep0[4*q+0], keep0[4*q+1], keep0[4*q+2], keep0[4*q+3]);
            cp1[q] = make_float4(keep1[4*q+0], keep1[4*q+1], keep1[4*q+2], keep1[4*q+3]);
        }
    }

    // ---- block 3: o = sigmoid(...); h_new = o * tanh(c_new) ----
    gate_block2(sWx, sWh, sB64, 3, x0, x1, h0, h1, a0, a1);
    unpack_block(a0, t0); unpack_block(a1, t1);
    float hn0[16], hn1[16];
    #pragma unroll
    for (int j = 0; j < 16; j++) {
        hn0[j] = sig_f(t0[j]) * tanh_f(keep0[j]);
        hn1[j] = sig_f(t1[j]) * tanh_f(keep1[j]);
    }

    // write h_new
    {
        float4* hp0 = (float4*)(out_h + cell0 * 16);
        float4* hp1 = (float4*)(out_h + cell1 * 16);
        #pragma unroll
        for (int q = 0; q < 4; q++) {
            hp0[q] = make_float4(hn0[4*q+0], hn0[4*q+1], hn0[4*q+2], hn0[4*q+3]);
            hp1[q] = make_float4(hn1[4*q+0], hn1[4*q+1], hn1[4*q+2], hn1[4*q+3]);
        }
    }

    // ---------------- output projection: out = tanh(h_new @ Wo + bo) ----------------
    float o0[9], o1[9];
    #pragma unroll
    for (int j = 0; j < 9; j++) {
        float a0s = sBo[j], a1s = sBo[j];
        const float4* wr = (const float4*)(sWoT + j * 16);
        #pragma unroll
        for (int q = 0; q < 4; q++) {
            float4 w = wr[q];
            a0s = fmaf(hn0[4*q+0], w.x, a0s); a1s = fmaf(hn1[4*q+0], w.x, a1s);
            a0s = fmaf(hn0[4*q+1], w.y, a0s); a1s = fmaf(hn1[4*q+1], w.y, a1s);
            a0s = fmaf(hn0[4*q+2], w.z, a0s); a1s = fmaf(hn1[4*q+2], w.z, a1s);
            a0s = fmaf(hn0[4*q+3], w.w, a0s); a1s = fmaf(hn1[4*q+3], w.w, a1s);
        }
        o0[j] = tanh_f(a0s);
        o1[j] = tanh_f(a1s);
    }

    out_dyn[cell0] = o0[0];
    out_dyn[cell1] = o1[0];
    {
        float4* lp0 = (float4*)(out_lat + cell0 * 8);
        float4* lp1 = (float4*)(out_lat + cell1 * 8);
        lp0[0] = make_float4(o0[1], o0[2], o0[3], o0[4]);
        lp0[1] = make_float4(o0[5], o0[6], o0[7], o0[8]);
        lp1[0] = make_float4(o1[1], o1[2], o1[3], o1[4]);
        lp1[1] = make_float4(o1[5], o1[6], o1[7], o1[8]);
    }
}

extern "C" void kernel_launch(void* const* d_in, const int* in_sizes, int n_in,
                              void* d_out, int out_size) {
    const float* dyn_in   = (const float*)d_in[0];
    const float* lat_in   = (const float*)d_in[1];
    const float* lat_out  = (const float*)d_in[2];
    const float* h        = (const float*)d_in[3];
    const float* c        = (const float*)d_in[4];
    const float* Wx       = (const float*)d_in[5];
    const float* Wh       = (const float*)d_in[6];
    const float* bvec     = (const float*)d_in[7];
    const float* Wo       = (const float*)d_in[8];
    const float* bo       = (const float*)d_in[9];
    // d_in[10..12] = pos0 / coming_from / going_to : adjacency recomputed analytically.

    float* out = (float*)d_out;
    float* out_dyn = out;                                   // [B, P, 1]
    float* out_lat = out_dyn + (size_t)NBATCH * NP;         // [B, P, 8]
    float* out_h   = out_lat + (size_t)NBATCH * NP * 8;     // [B, P, 16]
    float* out_c   = out_h   + (size_t)NBATCH * NP * 16;    // [B, P, 16]

    int total_threads = (NBATCH / 2) * NP;   // 2 cells (batch halves) per thread
    int blocks = total_threads / CTA;
    knet_kernel<<<blocks, CTA>>>(dyn_in, lat_in, lat_out, h, c,
                                 Wx, Wh, bvec, Wo, bo,
                                 out_dyn, out_lat, out_h, out_c);
}

// round 11
// speedup vs baseline: 1.1461x; 1.0715x over previous
#include <cuda_runtime.h>

#define NP 65536          // cells per batch (256*256)
#define NCOLS 256
#define NBATCH 32
#define CTA 128

typedef unsigned long long u64;

// All weights live in constant memory: warp-uniform, immediate-offset access
// compiles to the uniform constant port (LDCU/UR), off the L1 pipe entirely.
__constant__ float cWx[9 * 64];
__constant__ float cWh[16 * 64];
__constant__ float cB[64];
__constant__ float cWo[16 * 9];
__constant__ float cBo[9];

__device__ __forceinline__ float tanh_f(float x) {
    float y; asm("tanh.approx.f32 %0, %1;" : "=f"(y) : "f"(x)); return y;
}
__device__ __forceinline__ float sig_f(float x) {
    return fmaf(0.5f, tanh_f(0.5f * x), 0.5f);
}
__device__ __forceinline__ u64 pack2(float a, float b) {
    u64 v; asm("mov.b64 %0, {%1, %2};" : "=l"(v) : "f"(a), "f"(b)); return v;
}
__device__ __forceinline__ void unpack2(u64 v, float& a, float& b) {
    asm("mov.b64 {%0, %1}, %2;" : "=f"(a), "=f"(b) : "l"(v));
}
// packed f32x2 FMA: acc.lo += m.lo*w.lo ; acc.hi += m.hi*w.hi
#define FMA2(acc, m, w) asm("fma.rn.f32x2 %0, %1, %2, %0;" : "+l"(acc) : "l"(m), "l"(w))

// One 16-gate block (blk in {0:i,1:f,2:g,3:o}) for two cells, gate-pair packed.
// Weight pairs come from constant memory (uniform port), not shared/L1.
__device__ __forceinline__ void gate_block2(
    int blk,
    const float* x0, const float* x1,
    const float* h0, const float* h1,
    u64* a0, u64* a1)
{
    const u64* bp = (const u64*)(cB + blk * 16);
    #pragma unroll
    for (int j = 0; j < 8; j++) { u64 bv = bp[j]; a0[j] = bv; a1[j] = bv; }

    #pragma unroll
    for (int k = 0; k < 9; k++) {
        const u64* wr = (const u64*)(cWx + k * 64 + blk * 16);
        u64 xa = pack2(x0[k], x0[k]);
        u64 xb = pack2(x1[k], x1[k]);
        #pragma unroll
        for (int q = 0; q < 8; q++) {
            u64 w = wr[q];
            FMA2(a0[q], xa, w); FMA2(a1[q], xb, w);
        }
    }
    #pragma unroll
    for (int k = 0; k < 16; k++) {
        const u64* wr = (const u64*)(cWh + k * 64 + blk * 16);
        u64 ha = pack2(h0[k], h0[k]);
        u64 hb = pack2(h1[k], h1[k]);
        #pragma unroll
        for (int q = 0; q < 8; q++) {
            u64 w = wr[q];
            FMA2(a0[q], ha, w); FMA2(a1[q], hb, w);
        }
    }
}

__device__ __forceinline__ void unpack_block(const u64* a, float* out) {
    #pragma unroll
    for (int j = 0; j < 8; j++) unpack2(a[j], out[2*j], out[2*j+1]);
}

__global__ __launch_bounds__(CTA, 3) void knet_kernel(
    const float* __restrict__ dyn_in,
    const float* __restrict__ lat_in_g,
    const float* __restrict__ lat_out_g,
    const float* __restrict__ h_g,
    const float* __restrict__ c_g,
    float* __restrict__ out_dyn,
    float* __restrict__ out_lat,
    float* __restrict__ out_h,
    float* __restrict__ out_c)
{
    int tid = blockIdx.x * CTA + threadIdx.x;   // 0 .. 16*NP-1
    int p   = tid & (NP - 1);
    int b0  = tid >> 16;       // 0..15
    int b1  = b0 + 16;

    int r  = p >> 8;
    int cc = p & (NCOLS - 1);

    size_t cell0 = (size_t)b0 * NP + p;
    size_t cell1 = (size_t)b1 * NP + p;

    // ---------------- gather x = [dyn, lat_in(updated)] ----------------
    float x0[9], x1[9];
    x0[0] = dyn_in[cell0];
    x1[0] = dyn_in[cell1];
    {
        const float* lo0 = lat_out_g + ((size_t)b0 * NP) * 8;  // batch base
        const float* lo1 = lat_out_g + ((size_t)b1 * NP) * 8;
        const int drs[8] = {-1,-1,-1, 0, 0, 1, 1, 1};
        const int dcs[8] = {-1, 0, 1,-1, 1,-1, 0, 1};

        bool interior = (r > 0) & (r < 255) & (cc > 0) & (cc < 255);
        if (__all_sync(0xffffffffu, interior)) {
            // warp-uniform fast path: no border fallbacks, no predication
            #pragma unroll
            for (int d = 0; d < 8; d++) {
                int nb = (r + drs[d]) * NCOLS + (cc + dcs[d]);
                x0[1 + d] = lo0[(size_t)nb * 8 + d];
                x1[1 + d] = lo1[(size_t)nb * 8 + d];
            }
        } else {
            const float* li0 = lat_in_g + cell0 * 8;
            const float* li1 = lat_in_g + cell1 * 8;
            #pragma unroll
            for (int d = 0; d < 8; d++) {
                int nr = r + drs[d], nc = cc + dcs[d];
                bool valid = ((unsigned)nr < 256u) && ((unsigned)nc < 256u);
                int nb = nr * NCOLS + nc;
                float v0, v1;
                if (valid) {
                    v0 = lo0[(size_t)nb * 8 + d];
                    v1 = lo1[(size_t)nb * 8 + d];
                } else {
                    v0 = li0[d];
                    v1 = li1[d];
                }
                x0[1 + d] = v0;
                x1[1 + d] = v1;
            }
        }
    }

    // ---------------- load h ----------------
    float h0[16], h1[16];
    {
        const float4* hp0 = (const float4*)(h_g + cell0 * 16);
        const float4* hp1 = (const float4*)(h_g + cell1 * 16);
        #pragma unroll
        for (int q = 0; q < 4; q++) {
            float4 v0 = hp0[q], v1 = hp1[q];
            h0[4*q+0] = v0.x; h0[4*q+1] = v0.y; h0[4*q+2] = v0.z; h0[4*q+3] = v0.w;
            h1[4*q+0] = v1.x; h1[4*q+1] = v1.y; h1[4*q+2] = v1.z; h1[4*q+3] = v1.w;
        }
    }

    u64 a0[8], a1[8];
    float t0[16], t1[16];
    float keep0[16], keep1[16];   // holds g, then i*g, then c_new

    // ---- block 2: g = tanh(...) ----
    gate_block2(2, x0, x1, h0, h1, a0, a1);
    unpack_block(a0, t0); unpack_block(a1, t1);
    #pragma unroll
    for (int j = 0; j < 16; j++) { keep0[j] = tanh_f(t0[j]); keep1[j] = tanh_f(t1[j]); }

    // ---- block 0: i = sigmoid(...); keep = i*g ----
    gate_block2(0, x0, x1, h0, h1, a0, a1);
    unpack_block(a0, t0); unpack_block(a1, t1);
    #pragma unroll
    for (int j = 0; j < 16; j++) {
        keep0[j] = sig_f(t0[j]) * keep0[j];
        keep1[j] = sig_f(t1[j]) * keep1[j];
    }

    // ---- block 1: f = sigmoid(...); keep = c_new = f*c + i*g ----
    gate_block2(1, x0, x1, h0, h1, a0, a1);
    unpack_block(a0, t0); unpack_block(a1, t1);
    {
        const float4* cp0 = (const float4*)(c_g + cell0 * 16);
        const float4* cp1 = (const float4*)(c_g + cell1 * 16);
        #pragma unroll
        for (int q = 0; q < 4; q++) {
            float4 cv0 = cp0[q], cv1 = cp1[q];
            keep0[4*q+0] = fmaf(sig_f(t0[4*q+0]), cv0.x, keep0[4*q+0]);
            keep0[4*q+1] = fmaf(sig_f(t0[4*q+1]), cv0.y, keep0[4*q+1]);
            keep0[4*q+2] = fmaf(sig_f(t0[4*q+2]), cv0.z, keep0[4*q+2]);
            keep0[4*q+3] = fmaf(sig_f(t0[4*q+3]), cv0.w, keep0[4*q+3]);
            keep1[4*q+0] = fmaf(sig_f(t1[4*q+0]), cv1.x, keep1[4*q+0]);
            keep1[4*q+1] = fmaf(sig_f(t1[4*q+1]), cv1.y, keep1[4*q+1]);
            keep1[4*q+2] = fmaf(sig_f(t1[4*q+2]), cv1.z, keep1[4*q+2]);
            keep1[4*q+3] = fmaf(sig_f(t1[4*q+3]), cv1.w, keep1[4*q+3]);
        }
    }

    // write c_new
    {
        float4* cp0 = (float4*)(out_c + cell0 * 16);
        float4* cp1 = (float4*)(out_c + cell1 * 16);
        #pragma unroll
        for (int q = 0; q < 4; q++) {
            cp0[q] = make_float4(keep0[4*q+0], keep0[4*q+1], keep0[4*q+2], keep0[4*q+3]);
            cp1[q] = make_float4(keep1[4*q+0], keep1[4*q+1], keep1[4*q+2], keep1[4*q+3]);
        }
    }

    // ---- block 3: o = sigmoid(...); h_new = o * tanh(c_new) ----
    gate_block2(3, x0, x1, h0, h1, a0, a1);
    unpack_block(a0, t0); unpack_block(a1, t1);
    float hn0[16], hn1[16];
    #pragma unroll
    for (int j = 0; j < 16; j++) {
        hn0[j] = sig_f(t0[j]) * tanh_f(keep0[j]);
        hn1[j] = sig_f(t1[j]) * tanh_f(keep1[j]);
    }

    // write h_new
    {
        float4* hp0 = (float4*)(out_h + cell0 * 16);
        float4* hp1 = (float4*)(out_h + cell1 * 16);
        #pragma unroll
        for (int q = 0; q < 4; q++) {
            hp0[q] = make_float4(hn0[4*q+0], hn0[4*q+1], hn0[4*q+2], hn0[4*q+3]);
            hp1[q] = make_float4(hn1[4*q+0], hn1[4*q+1], hn1[4*q+2], hn1[4*q+3]);
        }
    }

    // ---------------- output projection: out = tanh(h_new @ Wo + bo) ----------------
    float o0[9], o1[9];
    #pragma unroll
    for (int j = 0; j < 9; j++) {
        float a0s = cBo[j], a1s = cBo[j];
        #pragma unroll
        for (int k = 0; k < 16; k++) {
            float w = cWo[k * 9 + j];
            a0s = fmaf(hn0[k], w, a0s);
            a1s = fmaf(hn1[k], w, a1s);
        }
        o0[j] = tanh_f(a0s);
        o1[j] = tanh_f(a1s);
    }

    out_dyn[cell0] = o0[0];
    out_dyn[cell1] = o1[0];
    {
        float4* lp0 = (float4*)(out_lat + cell0 * 8);
        float4* lp1 = (float4*)(out_lat + cell1 * 8);
        lp0[0] = make_float4(o0[1], o0[2], o0[3], o0[4]);
        lp0[1] = make_float4(o0[5], o0[6], o0[7], o0[8]);
        lp1[0] = make_float4(o1[1], o1[2], o1[3], o1[4]);
        lp1[1] = make_float4(o1[5], o1[6], o1[7], o1[8]);
    }
}

extern "C" void kernel_launch(void* const* d_in, const int* in_sizes, int n_in,
                              void* d_out, int out_size) {
    const float* dyn_in   = (const float*)d_in[0];
    const float* lat_in   = (const float*)d_in[1];
    const float* lat_out  = (const float*)d_in[2];
    const float* h        = (const float*)d_in[3];
    const float* c        = (const float*)d_in[4];
    const float* Wx       = (const float*)d_in[5];
    const float* Wh       = (const float*)d_in[6];
    const float* bvec     = (const float*)d_in[7];
    const float* Wo       = (const float*)d_in[8];
    const float* bo       = (const float*)d_in[9];
    // d_in[10..12] = pos0 / coming_from / going_to : adjacency recomputed analytically.

    // Stage weights into constant memory (D2D async copies: graph-capturable,
    // no allocation, deterministic).
    cudaMemcpyToSymbolAsync(cWx, Wx,   9 * 64 * sizeof(float), 0, cudaMemcpyDeviceToDevice);
    cudaMemcpyToSymbolAsync(cWh, Wh,  16 * 64 * sizeof(float), 0, cudaMemcpyDeviceToDevice);
    cudaMemcpyToSymbolAsync(cB,  bvec,     64 * sizeof(float), 0, cudaMemcpyDeviceToDevice);
    cudaMemcpyToSymbolAsync(cWo, Wo,  16 * 9 * sizeof(float), 0, cudaMemcpyDeviceToDevice);
    cudaMemcpyToSymbolAsync(cBo, bo,        9 * sizeof(float), 0, cudaMemcpyDeviceToDevice);

    float* out = (float*)d_out;
    float* out_dyn = out;                                   // [B, P, 1]
    float* out_lat = out_dyn + (size_t)NBATCH * NP;         // [B, P, 8]
    float* out_h   = out_lat + (size_t)NBATCH * NP * 8;     // [B, P, 16]
    float* out_c   = out_h   + (size_t)NBATCH * NP * 16;    // [B, P, 16]

    int total_threads = (NBATCH / 2) * NP;   // 2 cells (batch halves) per thread
    int blocks = total_threads / CTA;
    knet_kernel<<<blocks, CTA>>>(dyn_in, lat_in, lat_out, h, c,
                                 out_dyn, out_lat, out_h, out_c);
}

// round 12
// speedup vs baseline: 1.1757x; 1.0257x over previous
#include <cuda_runtime.h>

#define NP 65536          // cells per batch (256*256)
#define NCOLS 256
#define NBATCH 32
#define CTA 128

typedef unsigned long long u64;

// Wx + biases + Wo in constant memory (uniform port); Wh goes to SMEM so the
// two weight streams ride different HW ports (constant port floor-8 vs LDS).
__constant__ __align__(16) float cWx[9 * 64];
__constant__ __align__(16) float cB[64];
__constant__ __align__(16) float cWo[16 * 9];
__constant__ __align__(16) float cBo[9];

__device__ __forceinline__ float tanh_f(float x) {
    float y; asm("tanh.approx.f32 %0, %1;" : "=f"(y) : "f"(x)); return y;
}
__device__ __forceinline__ float sig_f(float x) {
    return fmaf(0.5f, tanh_f(0.5f * x), 0.5f);
}
__device__ __forceinline__ u64 pack2(float a, float b) {
    u64 v; asm("mov.b64 %0, {%1, %2};" : "=l"(v) : "f"(a), "f"(b)); return v;
}
__device__ __forceinline__ void unpack2(u64 v, float& a, float& b) {
    asm("mov.b64 {%0, %1}, %2;" : "=f"(a), "=f"(b) : "l"(v));
}
// packed f32x2 FMA: acc.lo += m.lo*w.lo ; acc.hi += m.hi*w.hi
#define FMA2(acc, m, w) asm("fma.rn.f32x2 %0, %1, %2, %0;" : "+l"(acc) : "l"(m), "l"(w))

// One 16-gate block (blk in {0:i,1:f,2:g,3:o}) for two cells, gate-pair packed.
// Wx pairs from constant port; Wh pairs from SMEM (LDS.128).
__device__ __forceinline__ void gate_block2(
    const float* sWh, int blk,
    const float* x0, const float* x1,
    const float* h0, const float* h1,
    u64* a0, u64* a1)
{
    const u64* bp = (const u64*)(cB + blk * 16);
    #pragma unroll
    for (int j = 0; j < 8; j++) { u64 bv = bp[j]; a0[j] = bv; a1[j] = bv; }

    #pragma unroll
    for (int k = 0; k < 9; k++) {
        const u64* wr = (const u64*)(cWx + k * 64 + blk * 16);
        u64 xa = pack2(x0[k], x0[k]);
        u64 xb = pack2(x1[k], x1[k]);
        #pragma unroll
        for (int q = 0; q < 8; q++) {
            u64 w = wr[q];
            FMA2(a0[q], xa, w); FMA2(a1[q], xb, w);
        }
    }
    #pragma unroll
    for (int k = 0; k < 16; k++) {
        const ulonglong2* wr = (const ulonglong2*)(sWh + k * 64 + blk * 16);
        u64 ha = pack2(h0[k], h0[k]);
        u64 hb = pack2(h1[k], h1[k]);
        #pragma unroll
        for (int q = 0; q < 4; q++) {
            ulonglong2 w = wr[q];
            FMA2(a0[2*q+0], ha, w.x); FMA2(a1[2*q+0], hb, w.x);
            FMA2(a0[2*q+1], ha, w.y); FMA2(a1[2*q+1], hb, w.y);
        }
    }
}

__global__ __launch_bounds__(CTA, 4) void knet_kernel(
    const float* __restrict__ dyn_in,
    const float* __restrict__ lat_in_g,
    const float* __restrict__ lat_out_g,
    const float* __restrict__ h_g,
    const float* __restrict__ c_g,
    const float* __restrict__ Wh_g,
    float* __restrict__ out_dyn,
    float* __restrict__ out_lat,
    float* __restrict__ out_h,
    float* __restrict__ out_c)
{
    __shared__ __align__(16) float sWh[16 * 64];
    for (int i = threadIdx.x; i < 16 * 64; i += CTA) sWh[i] = Wh_g[i];
    __syncthreads();

    int tid = blockIdx.x * CTA + threadIdx.x;   // 0 .. 16*NP-1
    int p   = tid & (NP - 1);
    int b0  = tid >> 16;       // 0..15
    int b1  = b0 + 16;

    int r  = p >> 8;
    int cc = p & (NCOLS - 1);

    size_t cell0 = (size_t)b0 * NP + p;
    size_t cell1 = (size_t)b1 * NP + p;

    // ---------------- gather x = [dyn, lat_in(updated)] ----------------
    float x0[9], x1[9];
    x0[0] = dyn_in[cell0];
    x1[0] = dyn_in[cell1];
    {
        const float* lo0 = lat_out_g + ((size_t)b0 * NP) * 8;  // batch base
        const float* lo1 = lat_out_g + ((size_t)b1 * NP) * 8;
        const int drs[8] = {-1,-1,-1, 0, 0, 1, 1, 1};
        const int dcs[8] = {-1, 0, 1,-1, 1,-1, 0, 1};

        bool interior = (r > 0) & (r < 255) & (cc > 0) & (cc < 255);
        if (__all_sync(0xffffffffu, interior)) {
            #pragma unroll
            for (int d = 0; d < 8; d++) {
                int nb = (r + drs[d]) * NCOLS + (cc + dcs[d]);
                x0[1 + d] = lo0[(size_t)nb * 8 + d];
                x1[1 + d] = lo1[(size_t)nb * 8 + d];
            }
        } else {
            const float* li0 = lat_in_g + cell0 * 8;
            const float* li1 = lat_in_g + cell1 * 8;
            #pragma unroll
            for (int d = 0; d < 8; d++) {
                int nr = r + drs[d], nc = cc + dcs[d];
                bool valid = ((unsigned)nr < 256u) && ((unsigned)nc < 256u);
                int nb = nr * NCOLS + nc;
                float v0, v1;
                if (valid) {
                    v0 = lo0[(size_t)nb * 8 + d];
                    v1 = lo1[(size_t)nb * 8 + d];
                } else {
                    v0 = li0[d];
                    v1 = li1[d];
                }
                x0[1 + d] = v0;
                x1[1 + d] = v1;
            }
        }
    }

    // ---------------- load h ----------------
    float h0[16], h1[16];
    {
        const float4* hp0 = (const float4*)(h_g + cell0 * 16);
        const float4* hp1 = (const float4*)(h_g + cell1 * 16);
        #pragma unroll
        for (int q = 0; q < 4; q++) {
            float4 v0 = hp0[q], v1 = hp1[q];
            h0[4*q+0] = v0.x; h0[4*q+1] = v0.y; h0[4*q+2] = v0.z; h0[4*q+3] = v0.w;
            h1[4*q+0] = v1.x; h1[4*q+1] = v1.y; h1[4*q+2] = v1.z; h1[4*q+3] = v1.w;
        }
    }

    u64 a0[8], a1[8];
    float keep0[16], keep1[16];   // g, then i*g, then c_new, then h_new

    // ---- block 2: g = tanh(...) ----
    gate_block2(sWh, 2, x0, x1, h0, h1, a0, a1);
    #pragma unroll
    for (int j = 0; j < 8; j++) {
        float f0, f1;
        unpack2(a0[j], f0, f1); keep0[2*j] = tanh_f(f0); keep0[2*j+1] = tanh_f(f1);
        unpack2(a1[j], f0, f1); keep1[2*j] = tanh_f(f0); keep1[2*j+1] = tanh_f(f1);
    }

    // ---- block 0: i = sigmoid(...); keep = i*g ----
    gate_block2(sWh, 0, x0, x1, h0, h1, a0, a1);
    #pragma unroll
    for (int j = 0; j < 8; j++) {
        float f0, f1;
        unpack2(a0[j], f0, f1); keep0[2*j] *= sig_f(f0); keep0[2*j+1] *= sig_f(f1);
        unpack2(a1[j], f0, f1); keep1[2*j] *= sig_f(f0); keep1[2*j+1] *= sig_f(f1);
    }

    // ---- block 1: f = sigmoid(...); keep = c_new = f*c + i*g ----
    gate_block2(sWh, 1, x0, x1, h0, h1, a0, a1);
    {
        const float4* cp0 = (const float4*)(c_g + cell0 * 16);
        const float4* cp1 = (const float4*)(c_g + cell1 * 16);
        #pragma unroll
        for (int q = 0; q < 4; q++) {
            float4 cv0 = cp0[q], cv1 = cp1[q];
            float f0, f1;
            unpack2(a0[2*q+0], f0, f1);
            keep0[4*q+0] = fmaf(sig_f(f0), cv0.x, keep0[4*q+0]);
            keep0[4*q+1] = fmaf(sig_f(f1), cv0.y, keep0[4*q+1]);
            unpack2(a0[2*q+1], f0, f1);
            keep0[4*q+2] = fmaf(sig_f(f0), cv0.z, keep0[4*q+2]);
            keep0[4*q+3] = fmaf(sig_f(f1), cv0.w, keep0[4*q+3]);
            unpack2(a1[2*q+0], f0, f1);
            keep1[4*q+0] = fmaf(sig_f(f0), cv1.x, keep1[4*q+0]);
            keep1[4*q+1] = fmaf(sig_f(f1), cv1.y, keep1[4*q+1]);
            unpack2(a1[2*q+1], f0, f1);
            keep1[4*q+2] = fmaf(sig_f(f0), cv1.z, keep1[4*q+2]);
            keep1[4*q+3] = fmaf(sig_f(f1), cv1.w, keep1[4*q+3]);
        }
    }

    // write c_new
    {
        float4* cp0 = (float4*)(out_c + cell0 * 16);
        float4* cp1 = (float4*)(out_c + cell1 * 16);
        #pragma unroll
        for (int q = 0; q < 4; q++) {
            cp0[q] = make_float4(keep0[4*q+0], keep0[4*q+1], keep0[4*q+2], keep0[4*q+3]);
            cp1[q] = make_float4(keep1[4*q+0], keep1[4*q+1], keep1[4*q+2], keep1[4*q+3]);
        }
    }

    // ---- block 3: o = sigmoid(...); keep = h_new = o * tanh(c_new) ----
    gate_block2(sWh, 3, x0, x1, h0, h1, a0, a1);
    #pragma unroll
    for (int j = 0; j < 8; j++) {
        float f0, f1;
        unpack2(a0[j], f0, f1);
        keep0[2*j]   = sig_f(f0) * tanh_f(keep0[2*j]);
        keep0[2*j+1] = sig_f(f1) * tanh_f(keep0[2*j+1]);
        unpack2(a1[j], f0, f1);
        keep1[2*j]   = sig_f(f0) * tanh_f(keep1[2*j]);
        keep1[2*j+1] = sig_f(f1) * tanh_f(keep1[2*j+1]);
    }

    // write h_new
    {
        float4* hp0 = (float4*)(out_h + cell0 * 16);
        float4* hp1 = (float4*)(out_h + cell1 * 16);
        #pragma unroll
        for (int q = 0; q < 4; q++) {
            hp0[q] = make_float4(keep0[4*q+0], keep0[4*q+1], keep0[4*q+2], keep0[4*q+3]);
            hp1[q] = make_float4(keep1[4*q+0], keep1[4*q+1], keep1[4*q+2], keep1[4*q+3]);
        }
    }

    // ---------------- output projection: out = tanh(h_new @ Wo + bo) ----------------
    float o0[9], o1[9];
    #pragma unroll
    for (int j = 0; j < 9; j++) {
        float a0s = cBo[j], a1s = cBo[j];
        #pragma unroll
        for (int k = 0; k < 16; k++) {
            float w = cWo[k * 9 + j];
            a0s = fmaf(keep0[k], w, a0s);
            a1s = fmaf(keep1[k], w, a1s);
        }
        o0[j] = tanh_f(a0s);
        o1[j] = tanh_f(a1s);
    }

    out_dyn[cell0] = o0[0];
    out_dyn[cell1] = o1[0];
    {
        float4* lp0 = (float4*)(out_lat + cell0 * 8);
        float4* lp1 = (float4*)(out_lat + cell1 * 8);
        lp0[0] = make_float4(o0[1], o0[2], o0[3], o0[4]);
        lp0[1] = make_float4(o0[5], o0[6], o0[7], o0[8]);
        lp1[0] = make_float4(o1[1], o1[2], o1[3], o1[4]);
        lp1[1] = make_float4(o1[5], o1[6], o1[7], o1[8]);
    }
}

extern "C" void kernel_launch(void* const* d_in, const int* in_sizes, int n_in,
                              void* d_out, int out_size) {
    const float* dyn_in   = (const float*)d_in[0];
    const float* lat_in   = (const float*)d_in[1];
    const float* lat_out  = (const float*)d_in[2];
    const float* h        = (const float*)d_in[3];
    const float* c        = (const float*)d_in[4];
    const float* Wx       = (const float*)d_in[5];
    const float* Wh       = (const float*)d_in[6];
    const float* bvec     = (const float*)d_in[7];
    const float* Wo       = (const float*)d_in[8];
    const float* bo       = (const float*)d_in[9];
    // d_in[10..12] = pos0 / coming_from / going_to : adjacency recomputed analytically.

    // Stage small weights into constant memory (D2D async, graph-capturable).
    cudaMemcpyToSymbolAsync(cWx, Wx,   9 * 64 * sizeof(float), 0, cudaMemcpyDeviceToDevice);
    cudaMemcpyToSymbolAsync(cB,  bvec,     64 * sizeof(float), 0, cudaMemcpyDeviceToDevice);
    cudaMemcpyToSymbolAsync(cWo, Wo,  16 * 9 * sizeof(float), 0, cudaMemcpyDeviceToDevice);
    cudaMemcpyToSymbolAsync(cBo, bo,        9 * sizeof(float), 0, cudaMemcpyDeviceToDevice);

    float* out = (float*)d_out;
    float* out_dyn = out;                                   // [B, P, 1]
    float* out_lat = out_dyn + (size_t)NBATCH * NP;         // [B, P, 8]
    float* out_h   = out_lat + (size_t)NBATCH * NP * 8;     // [B, P, 16]
    float* out_c   = out_h   + (size_t)NBATCH * NP * 16;    // [B, P, 16]

    int total_threads = (NBATCH / 2) * NP;   // 2 cells (batch halves) per thread
    int blocks = total_threads / CTA;
    knet_kernel<<<blocks, CTA>>>(dyn_in, lat_in, lat_out, h, c, Wh,
                                 out_dyn, out_lat, out_h, out_c);
}